// round 10
// baseline (speedup 1.0000x reference)
#include <cuda_runtime.h>
#include <cuda_fp16.h>
#include <cstdint>

// SpatialAttention: B=4, C=128, HW=4096
// out[n,e,t] = sum_s V[n,e,s] * softmax_s( sum_c K[n,c,s]*Q[n,c,t] / sqrt(C) )
// fp16 m16n8k16 mma.sync; fp16-preconverted K/V fed by 4-stage cp.async ring;
// GEMM1(it+1) pipelined ahead of GEMM2(it); P kept in registers.
// R10: 64-query CTAs (128 thr) at occupancy 2 -> two independent CTAs per SM
//      decouple barrier phases; batched ldsm issue lengthens RAW distance.

#define HW    4096
#define CD    128
#define TT    64             // queries (t) per CTA
#define BS    32             // keys (s) per iteration
#define NITER 128
#define NTH   128            // 4 warps, each owns 16 t-rows
#define RS    80             // smem row stride bytes (64B data + 16B pad)
#define TILE_B   (128 * RS)          // 10240 B per tile
#define STAGE_B  (2 * TILE_B)        // K + V per stage
#define NSTAGE   4
#define SMEM_BYTES (NSTAGE * STAGE_B)   // 81920 B (x2 CTAs = 160 KB/SM)

#define ELEMS (4 * CD * HW)   // per tensor, all batches

__device__ __half KhBuf[ELEMS];
__device__ __half VhBuf[ELEMS];

__device__ __forceinline__ uint32_t h2(float lo, float hi) {
    __half2 h = __floats2half2_rn(lo, hi);
    return *reinterpret_cast<uint32_t*>(&h);
}
__device__ __forceinline__ float ex2(float x) {
    float r; asm("ex2.approx.ftz.f32 %0, %1;" : "=f"(r) : "f"(x)); return r;
}
__device__ __forceinline__ void ldsm4t(uint32_t& r0, uint32_t& r1, uint32_t& r2, uint32_t& r3,
                                       uint32_t a) {
    asm volatile("ldmatrix.sync.aligned.m8n8.x4.trans.shared.b16 {%0,%1,%2,%3}, [%4];"
                 : "=r"(r0), "=r"(r1), "=r"(r2), "=r"(r3) : "r"(a));
}
__device__ __forceinline__ void ldsm4(uint32_t& r0, uint32_t& r1, uint32_t& r2, uint32_t& r3,
                                      uint32_t a) {
    asm volatile("ldmatrix.sync.aligned.m8n8.x4.shared.b16 {%0,%1,%2,%3}, [%4];"
                 : "=r"(r0), "=r"(r1), "=r"(r2), "=r"(r3) : "r"(a));
}
__device__ __forceinline__ void mma16816(float* c, const uint32_t* a, uint32_t b0, uint32_t b1) {
    asm volatile("mma.sync.aligned.m16n8k16.row.col.f32.f16.f16.f32 "
                 "{%0,%1,%2,%3}, {%4,%5,%6,%7}, {%8,%9}, {%0,%1,%2,%3};"
                 : "+f"(c[0]), "+f"(c[1]), "+f"(c[2]), "+f"(c[3])
                 : "r"(a[0]), "r"(a[1]), "r"(a[2]), "r"(a[3]), "r"(b0), "r"(b1));
}
__device__ __forceinline__ void cpasync16(uint32_t saddr, const void* gaddr) {
    asm volatile("cp.async.cg.shared.global [%0], [%1], 16;" :: "r"(saddr), "l"(gaddr));
}

// ---- pre-pass: f32 -> f16 for K and V ----
__global__ void __launch_bounds__(256) convert_kv(const float* __restrict__ K,
                                                  const float* __restrict__ V)
{
    size_t i = ((size_t)blockIdx.x * 256 + threadIdx.x) * 8;
    float4 a = *(const float4*)(K + i);
    float4 b = *(const float4*)(K + i + 4);
    *(uint4*)(KhBuf + i) = make_uint4(h2(a.x, a.y), h2(a.z, a.w), h2(b.x, b.y), h2(b.z, b.w));
    a = *(const float4*)(V + i);
    b = *(const float4*)(V + i + 4);
    *(uint4*)(VhBuf + i) = make_uint4(h2(a.x, a.y), h2(a.z, a.w), h2(b.x, b.y), h2(b.z, b.w));
}

__global__ void __launch_bounds__(NTH, 2)
spatial_attn_h3(const float* __restrict__ Qg, float* __restrict__ Og)
{
    extern __shared__ char smem[];
    const uint32_t sb = (uint32_t)__cvta_generic_to_shared(smem);
    const int tid  = threadIdx.x;
    const int warp = tid >> 5;
    const int lane = tid & 31;
    const int g    = lane >> 2;
    const int tg   = lane & 3;

    const size_t boff = (size_t)blockIdx.y * CD * HW;
    const float*  Qb  = Qg + boff;
    float*        Ob  = Og + boff;
    const __half* KhB = KhBuf + boff;
    const __half* VhB = VhBuf + boff;

    const int tw = blockIdx.x * TT + warp * 16;   // this warp's first t

    // ---- Q A-fragments, scaled by (1/sqrt(C))*log2(e), fp16 ----
    const float S = (float)(0.08838834764831845 * 1.4426950408889634);
    uint32_t qa[8][4];
#pragma unroll
    for (int kt = 0; kt < 8; kt++) {
        const float* q0 = Qb + (size_t)(kt * 16 + 2 * tg) * HW;
        qa[kt][0] = h2(q0[tw + g] * S,              q0[HW + tw + g] * S);
        qa[kt][1] = h2(q0[tw + g + 8] * S,          q0[HW + tw + g + 8] * S);
        qa[kt][2] = h2(q0[8 * HW + tw + g] * S,     q0[9 * HW + tw + g] * S);
        qa[kt][3] = h2(q0[8 * HW + tw + g + 8] * S, q0[9 * HW + tw + g + 8] * S);
    }

    float o[16][4];
#pragma unroll
    for (int ne = 0; ne < 16; ne++)
#pragma unroll
        for (int r = 0; r < 4; r++) o[ne][r] = 0.f;
    float l0 = 0.f, l1 = 0.f;

    // ---- cp.async stage loader: 512 16B-chunks per tensor, 4+4 per thread ----
    auto issueStage = [&](int it) {
        const int st = it & (NSTAGE - 1);
        const uint32_t kdst = sb + st * STAGE_B;
        const uint32_t vdst = kdst + TILE_B;
        const __half* ks = KhB + (size_t)it * BS;
        const __half* vs = VhB + (size_t)it * BS;
#pragma unroll
        for (int p = 0; p < 4; p++) {
            int ci  = tid + p * NTH;
            int row = ci >> 2;
            int ch  = ci & 3;
            uint32_t d = (uint32_t)(row * RS + ch * 16);
            size_t   s = (size_t)row * HW + ch * 8;
            cpasync16(kdst + d, ks + s);
            cpasync16(vdst + d, vs + s);
        }
    };

    // ---- GEMM1: scoresT[t][s] = Qs·K ; batch 4 ldsm per chunk, then 8 mma ----
    auto gemm1 = [&](int st, float sc[4][4]) {
#pragma unroll
        for (int ns = 0; ns < 4; ns++)
#pragma unroll
            for (int r = 0; r < 4; r++) sc[ns][r] = 0.f;
        const uint32_t ka = sb + st * STAGE_B + lane * RS;
#pragma unroll
        for (int i = 0; i < 4; i++) {
            uint32_t f[4][4];
#pragma unroll
            for (int ns = 0; ns < 4; ns++)
                ldsm4t(f[ns][0], f[ns][1], f[ns][2], f[ns][3],
                       ka + i * (32 * RS) + ns * 16);
#pragma unroll
            for (int ns = 0; ns < 4; ns++) {
                mma16816(sc[ns], qa[2 * i],     f[ns][0], f[ns][1]);
                mma16816(sc[ns], qa[2 * i + 1], f[ns][2], f[ns][3]);
            }
        }
    };

    // ---- prologue: fill 3 stages, then GEMM1(0) ----
    issueStage(0); asm volatile("cp.async.commit_group;");
    issueStage(1); asm volatile("cp.async.commit_group;");
    issueStage(2); asm volatile("cp.async.commit_group;");
    asm volatile("cp.async.wait_group 1;");
    __syncthreads();

    float sc[4][4];
    gemm1(0, sc);

    for (int it = 0; it < NITER; it++) {
        // ---- softmax of iter it (scores pre-scaled to log2 domain) ----
        uint32_t pa[2][4];
#pragma unroll
        for (int ns = 0; ns < 4; ns++) {
            float p0 = ex2(sc[ns][0]);
            float p1 = ex2(sc[ns][1]);
            float p2 = ex2(sc[ns][2]);
            float p3 = ex2(sc[ns][3]);
            l0 += p0 + p1;
            l1 += p2 + p3;
            pa[ns >> 1][(ns & 1) * 2 + 0] = h2(p0, p1);   // rows g
            pa[ns >> 1][(ns & 1) * 2 + 1] = h2(p2, p3);   // rows g+8
        }

        // ---- GEMM1(it+1) first: independent mma stream ahead of GEMM2(it) ----
        if (it + 1 < NITER) {
            asm volatile("cp.async.wait_group 1;");
            __syncthreads();
            gemm1((it + 1) & (NSTAGE - 1), sc);
        }

        // ---- GEMM2(it): O += P·V ; ldsm pairs ahead of mma quads ----
        {
            const uint32_t va = sb + (it & (NSTAGE - 1)) * STAGE_B + TILE_B
                              + (lane & 7) * RS + (lane >> 3) * 16;
#pragma unroll
            for (int np = 0; np < 8; np++) {
                uint32_t f0[4], f1[4];
                ldsm4(f0[0], f0[1], f0[2], f0[3], va + (2 * np)     * (8 * RS));
                ldsm4(f1[0], f1[1], f1[2], f1[3], va + (2 * np + 1) * (8 * RS));
                mma16816(o[2 * np],     pa[0], f0[0], f0[1]);
                mma16816(o[2 * np],     pa[1], f0[2], f0[3]);
                mma16816(o[2 * np + 1], pa[0], f1[0], f1[1]);
                mma16816(o[2 * np + 1], pa[1], f1[2], f1[3]);
            }
        }

        // ---- prefetch stage it+3 (empty commit keeps group count uniform) ----
        if (it + 3 < NITER) issueStage(it + 3);
        asm volatile("cp.async.commit_group;");
    }

    // ---- epilogue: finish row sums (quad reduce), normalize, store ----
    l0 += __shfl_xor_sync(0xffffffffu, l0, 1);
    l0 += __shfl_xor_sync(0xffffffffu, l0, 2);
    l1 += __shfl_xor_sync(0xffffffffu, l1, 1);
    l1 += __shfl_xor_sync(0xffffffffu, l1, 2);
    const float i0 = 1.0f / l0;
    const float i1 = 1.0f / l1;

#pragma unroll
    for (int ne = 0; ne < 16; ne++) {
        int e = ne * 8 + 2 * tg;
        Ob[(size_t)e       * HW + tw + g]     = o[ne][0] * i0;
        Ob[(size_t)(e + 1) * HW + tw + g]     = o[ne][1] * i0;
        Ob[(size_t)e       * HW + tw + g + 8] = o[ne][2] * i1;
        Ob[(size_t)(e + 1) * HW + tw + g + 8] = o[ne][3] * i1;
    }
}

extern "C" void kernel_launch(void* const* d_in, const int* in_sizes, int n_in,
                              void* d_out, int out_size)
{
    const float* K = (const float*)d_in[0];   // key
    const float* Q = (const float*)d_in[1];   // query
    const float* V = (const float*)d_in[2];   // value
    float*       O = (float*)d_out;

    const int nbatch = in_sizes[0] / (CD * HW);   // 4

    // pre-pass: K,V -> fp16 device buffers
    convert_kv<<<ELEMS / (256 * 8), 256>>>(K, V);

    cudaFuncSetAttribute(spatial_attn_h3,
                         cudaFuncAttributeMaxDynamicSharedMemorySize, SMEM_BYTES);
    dim3 grid(HW / TT, nbatch);   // (64, 4) = 256 CTAs, occupancy 2
    spatial_attn_h3<<<grid, NTH, SMEM_BYTES>>>(Q, O);
}

// round 11
// speedup vs baseline: 1.0124x; 1.0124x over previous
#include <cuda_runtime.h>
#include <cuda_fp16.h>
#include <cstdint>

// SpatialAttention: B=4, C=128, HW=4096
// out[n,e,t] = sum_s V[n,e,s] * softmax_s( sum_c K[n,c,s]*Q[n,c,t] / sqrt(C) )
// fp16 m16n8k16 mma.sync; fp16-preconverted K/V fed by 4-stage cp.async ring.
// R11: one barrier per iter + fused interleaved GEMM1(it+1)/GEMM2(it) block.

#define HW    4096
#define CD    128
#define TT    128            // queries (t) per CTA
#define BS    32             // keys (s) per iteration
#define NITER 128
#define NTH   256            // 8 warps, each owns 16 t-rows
#define RS    80             // smem row stride bytes (64B data + 16B pad)
#define TILE_B   (128 * RS)          // 10240 B per tile
#define STAGE_B  (2 * TILE_B)        // K + V per stage
#define NSTAGE   4
#define SMEM_BYTES (NSTAGE * STAGE_B)   // 81920 B

#define ELEMS (4 * CD * HW)   // per tensor, all batches

__device__ __half KhBuf[ELEMS];
__device__ __half VhBuf[ELEMS];

__device__ __forceinline__ uint32_t h2(float lo, float hi) {
    __half2 h = __floats2half2_rn(lo, hi);
    return *reinterpret_cast<uint32_t*>(&h);
}
__device__ __forceinline__ float ex2(float x) {
    float r; asm("ex2.approx.ftz.f32 %0, %1;" : "=f"(r) : "f"(x)); return r;
}
__device__ __forceinline__ void ldsm4t(uint32_t& r0, uint32_t& r1, uint32_t& r2, uint32_t& r3,
                                       uint32_t a) {
    asm volatile("ldmatrix.sync.aligned.m8n8.x4.trans.shared.b16 {%0,%1,%2,%3}, [%4];"
                 : "=r"(r0), "=r"(r1), "=r"(r2), "=r"(r3) : "r"(a));
}
__device__ __forceinline__ void ldsm4(uint32_t& r0, uint32_t& r1, uint32_t& r2, uint32_t& r3,
                                      uint32_t a) {
    asm volatile("ldmatrix.sync.aligned.m8n8.x4.shared.b16 {%0,%1,%2,%3}, [%4];"
                 : "=r"(r0), "=r"(r1), "=r"(r2), "=r"(r3) : "r"(a));
}
__device__ __forceinline__ void mma16816(float* c, const uint32_t* a, uint32_t b0, uint32_t b1) {
    asm volatile("mma.sync.aligned.m16n8k16.row.col.f32.f16.f16.f32 "
                 "{%0,%1,%2,%3}, {%4,%5,%6,%7}, {%8,%9}, {%0,%1,%2,%3};"
                 : "+f"(c[0]), "+f"(c[1]), "+f"(c[2]), "+f"(c[3])
                 : "r"(a[0]), "r"(a[1]), "r"(a[2]), "r"(a[3]), "r"(b0), "r"(b1));
}
__device__ __forceinline__ void cpasync16(uint32_t saddr, const void* gaddr) {
    asm volatile("cp.async.cg.shared.global [%0], [%1], 16;" :: "r"(saddr), "l"(gaddr));
}

// ---- pre-pass: f32 -> f16 for K and V ----
__global__ void __launch_bounds__(256) convert_kv(const float* __restrict__ K,
                                                  const float* __restrict__ V)
{
    size_t i = ((size_t)blockIdx.x * 256 + threadIdx.x) * 8;
    float4 a = *(const float4*)(K + i);
    float4 b = *(const float4*)(K + i + 4);
    *(uint4*)(KhBuf + i) = make_uint4(h2(a.x, a.y), h2(a.z, a.w), h2(b.x, b.y), h2(b.z, b.w));
    a = *(const float4*)(V + i);
    b = *(const float4*)(V + i + 4);
    *(uint4*)(VhBuf + i) = make_uint4(h2(a.x, a.y), h2(a.z, a.w), h2(b.x, b.y), h2(b.z, b.w));
}

__global__ void __launch_bounds__(NTH, 1)
spatial_attn_h4(const float* __restrict__ Qg, float* __restrict__ Og)
{
    extern __shared__ char smem[];
    const uint32_t sb = (uint32_t)__cvta_generic_to_shared(smem);
    const int tid  = threadIdx.x;
    const int warp = tid >> 5;
    const int lane = tid & 31;
    const int g    = lane >> 2;
    const int tg   = lane & 3;

    const size_t boff = (size_t)blockIdx.y * CD * HW;
    const float*  Qb  = Qg + boff;
    float*        Ob  = Og + boff;
    const __half* KhB = KhBuf + boff;
    const __half* VhB = VhBuf + boff;

    const int tw = blockIdx.x * TT + warp * 16;   // this warp's first t

    // ---- Q A-fragments, scaled by (1/sqrt(C))*log2(e), fp16 ----
    const float S = (float)(0.08838834764831845 * 1.4426950408889634);
    uint32_t qa[8][4];
#pragma unroll
    for (int kt = 0; kt < 8; kt++) {
        const float* q0 = Qb + (size_t)(kt * 16 + 2 * tg) * HW;
        qa[kt][0] = h2(q0[tw + g] * S,              q0[HW + tw + g] * S);
        qa[kt][1] = h2(q0[tw + g + 8] * S,          q0[HW + tw + g + 8] * S);
        qa[kt][2] = h2(q0[8 * HW + tw + g] * S,     q0[9 * HW + tw + g] * S);
        qa[kt][3] = h2(q0[8 * HW + tw + g + 8] * S, q0[9 * HW + tw + g + 8] * S);
    }

    float o[16][4];
#pragma unroll
    for (int ne = 0; ne < 16; ne++)
#pragma unroll
        for (int r = 0; r < 4; r++) o[ne][r] = 0.f;
    float l0 = 0.f, l1 = 0.f;

    // ---- cp.async stage loader: 512 16B-chunks per tensor, 2+2 per thread ----
    auto issueStage = [&](int it) {
        const int st = it & (NSTAGE - 1);
        const uint32_t kdst = sb + st * STAGE_B;
        const uint32_t vdst = kdst + TILE_B;
        const __half* ks = KhB + (size_t)it * BS;
        const __half* vs = VhB + (size_t)it * BS;
#pragma unroll
        for (int p = 0; p < 2; p++) {
            int ci  = tid + p * NTH;
            int row = ci >> 2;
            int ch  = ci & 3;
            uint32_t d = (uint32_t)(row * RS + ch * 16);
            size_t   s = (size_t)row * HW + ch * 8;
            cpasync16(kdst + d, ks + s);
            cpasync16(vdst + d, vs + s);
        }
    };

    // ---- prologue: fill 3 stages, then GEMM1(0) ----
    issueStage(0); asm volatile("cp.async.commit_group;");
    issueStage(1); asm volatile("cp.async.commit_group;");
    issueStage(2); asm volatile("cp.async.commit_group;");
    asm volatile("cp.async.wait_group 1;");
    __syncthreads();

    float sc[4][4];
    {   // GEMM1(0), standalone
#pragma unroll
        for (int ns = 0; ns < 4; ns++)
#pragma unroll
            for (int r = 0; r < 4; r++) sc[ns][r] = 0.f;
        const uint32_t ka = sb + lane * RS;
#pragma unroll
        for (int i = 0; i < 4; i++) {
            uint32_t f[4][4];
#pragma unroll
            for (int ns = 0; ns < 4; ns++)
                ldsm4t(f[ns][0], f[ns][1], f[ns][2], f[ns][3],
                       ka + i * (32 * RS) + ns * 16);
#pragma unroll
            for (int ns = 0; ns < 4; ns++) {
                mma16816(sc[ns], qa[2 * i],     f[ns][0], f[ns][1]);
                mma16816(sc[ns], qa[2 * i + 1], f[ns][2], f[ns][3]);
            }
        }
    }

    for (int it = 0; it < NITER; it++) {
        // ---- softmax of iter it (scores pre-scaled to log2 domain) ----
        uint32_t pa[2][4];
#pragma unroll
        for (int ns = 0; ns < 4; ns++) {
            float p0 = ex2(sc[ns][0]);
            float p1 = ex2(sc[ns][1]);
            float p2 = ex2(sc[ns][2]);
            float p3 = ex2(sc[ns][3]);
            l0 += p0 + p1;
            l1 += p2 + p3;
            pa[ns >> 1][(ns & 1) * 2 + 0] = h2(p0, p1);   // rows g
            pa[ns >> 1][(ns & 1) * 2 + 1] = h2(p2, p3);   // rows g+8
        }

        // ---- single barrier: publish stage it+1, protect reuse of it-1 ----
        if (it + 1 < NITER) asm volatile("cp.async.wait_group 1;");
        __syncthreads();

        const uint32_t va = sb + (it & (NSTAGE - 1)) * STAGE_B + TILE_B
                          + (lane & 7) * RS + (lane >> 3) * 16;

        if (it + 1 < NITER) {
            // ---- fused: GEMM1(it+1) interleaved with GEMM2(it) ----
#pragma unroll
            for (int ns = 0; ns < 4; ns++)
#pragma unroll
                for (int r = 0; r < 4; r++) sc[ns][r] = 0.f;
            const uint32_t ka = sb + ((it + 1) & (NSTAGE - 1)) * STAGE_B + lane * RS;
#pragma unroll
            for (int i = 0; i < 4; i++) {
                uint32_t fk[4][4];
#pragma unroll
                for (int ns = 0; ns < 4; ns++)
                    ldsm4t(fk[ns][0], fk[ns][1], fk[ns][2], fk[ns][3],
                           ka + i * (32 * RS) + ns * 16);
                uint32_t fv[4][4];
#pragma unroll
                for (int j = 0; j < 4; j++)
                    ldsm4(fv[j][0], fv[j][1], fv[j][2], fv[j][3],
                          va + (4 * i + j) * (8 * RS));
#pragma unroll
                for (int ns = 0; ns < 4; ns++) {
                    mma16816(sc[ns], qa[2 * i],     fk[ns][0], fk[ns][1]);
                    mma16816(sc[ns], qa[2 * i + 1], fk[ns][2], fk[ns][3]);
                }
#pragma unroll
                for (int j = 0; j < 4; j++) {
                    int ne = 4 * i + j;
                    mma16816(o[ne], pa[0], fv[j][0], fv[j][1]);
                    mma16816(o[ne], pa[1], fv[j][2], fv[j][3]);
                }
            }
        } else {
            // ---- tail: GEMM2(last) only ----
#pragma unroll
            for (int ne = 0; ne < 16; ne++) {
                uint32_t f0[4];
                ldsm4(f0[0], f0[1], f0[2], f0[3], va + ne * (8 * RS));
                mma16816(o[ne], pa[0], f0[0], f0[1]);
                mma16816(o[ne], pa[1], f0[2], f0[3]);
            }
        }

        // ---- prefetch stage it+3 (empty commit keeps group count uniform) ----
        if (it + 3 < NITER) issueStage(it + 3);
        asm volatile("cp.async.commit_group;");
    }

    // ---- epilogue: finish row sums (quad reduce), normalize, store ----
    l0 += __shfl_xor_sync(0xffffffffu, l0, 1);
    l0 += __shfl_xor_sync(0xffffffffu, l0, 2);
    l1 += __shfl_xor_sync(0xffffffffu, l1, 1);
    l1 += __shfl_xor_sync(0xffffffffu, l1, 2);
    const float i0 = 1.0f / l0;
    const float i1 = 1.0f / l1;

#pragma unroll
    for (int ne = 0; ne < 16; ne++) {
        int e = ne * 8 + 2 * tg;
        Ob[(size_t)e       * HW + tw + g]     = o[ne][0] * i0;
        Ob[(size_t)(e + 1) * HW + tw + g]     = o[ne][1] * i0;
        Ob[(size_t)e       * HW + tw + g + 8] = o[ne][2] * i1;
        Ob[(size_t)(e + 1) * HW + tw + g + 8] = o[ne][3] * i1;
    }
}

extern "C" void kernel_launch(void* const* d_in, const int* in_sizes, int n_in,
                              void* d_out, int out_size)
{
    const float* K = (const float*)d_in[0];   // key
    const float* Q = (const float*)d_in[1];   // query
    const float* V = (const float*)d_in[2];   // value
    float*       O = (float*)d_out;

    const int nbatch = in_sizes[0] / (CD * HW);   // 4

    // pre-pass: K,V -> fp16 device buffers
    convert_kv<<<ELEMS / (256 * 8), 256>>>(K, V);

    cudaFuncSetAttribute(spatial_attn_h4,
                         cudaFuncAttributeMaxDynamicSharedMemorySize, SMEM_BYTES);
    dim3 grid(HW / TT, nbatch);   // (32, 4) = 128 CTAs
    spatial_attn_h4<<<grid, NTH, SMEM_BYTES>>>(Q, O);
}

// round 12
// speedup vs baseline: 1.1561x; 1.1419x over previous
#include <cuda_runtime.h>
#include <cuda_fp16.h>
#include <cstdint>

// SpatialAttention: B=4, C=128, HW=4096
// out[n,e,t] = sum_s V[n,e,s] * softmax_s( sum_c K[n,c,s]*Q[n,c,t] / sqrt(C) )
// fp16 m16n8k16 mma.sync; fp16-preconverted K/V fed by 3-stage cp.async ring.
// R12: 64-s stages (two R9-style 32-s blocks per barrier) -> half the
//      rendezvous overhead; inner blocks identical to the proven R9 code.

#define HW    4096
#define CD    128
#define TT    128            // queries (t) per CTA
#define BS    64             // keys (s) per stage
#define NST   64             // stages
#define NVB   128            // virtual 32-s blocks
#define NTH   256            // 8 warps, each owns 16 t-rows
#define RS    144            // smem row stride bytes (128B data + 16B pad)
#define TILE_B   (128 * RS)          // 18432 B per tile (K or V)
#define STAGE_B  (2 * TILE_B)        // 36864 B
#define NSTAGE   3
#define SMEM_BYTES (NSTAGE * STAGE_B)   // 110592 B

#define ELEMS (4 * CD * HW)   // per tensor, all batches

__device__ __half KhBuf[ELEMS];
__device__ __half VhBuf[ELEMS];

__device__ __forceinline__ uint32_t h2(float lo, float hi) {
    __half2 h = __floats2half2_rn(lo, hi);
    return *reinterpret_cast<uint32_t*>(&h);
}
__device__ __forceinline__ float ex2(float x) {
    float r; asm("ex2.approx.ftz.f32 %0, %1;" : "=f"(r) : "f"(x)); return r;
}
__device__ __forceinline__ void ldsm4t(uint32_t& r0, uint32_t& r1, uint32_t& r2, uint32_t& r3,
                                       uint32_t a) {
    asm volatile("ldmatrix.sync.aligned.m8n8.x4.trans.shared.b16 {%0,%1,%2,%3}, [%4];"
                 : "=r"(r0), "=r"(r1), "=r"(r2), "=r"(r3) : "r"(a));
}
__device__ __forceinline__ void ldsm4(uint32_t& r0, uint32_t& r1, uint32_t& r2, uint32_t& r3,
                                      uint32_t a) {
    asm volatile("ldmatrix.sync.aligned.m8n8.x4.shared.b16 {%0,%1,%2,%3}, [%4];"
                 : "=r"(r0), "=r"(r1), "=r"(r2), "=r"(r3) : "r"(a));
}
__device__ __forceinline__ void mma16816(float* c, const uint32_t* a, uint32_t b0, uint32_t b1) {
    asm volatile("mma.sync.aligned.m16n8k16.row.col.f32.f16.f16.f32 "
                 "{%0,%1,%2,%3}, {%4,%5,%6,%7}, {%8,%9}, {%0,%1,%2,%3};"
                 : "+f"(c[0]), "+f"(c[1]), "+f"(c[2]), "+f"(c[3])
                 : "r"(a[0]), "r"(a[1]), "r"(a[2]), "r"(a[3]), "r"(b0), "r"(b1));
}
__device__ __forceinline__ void cpasync16(uint32_t saddr, const void* gaddr) {
    asm volatile("cp.async.cg.shared.global [%0], [%1], 16;" :: "r"(saddr), "l"(gaddr));
}

// ---- pre-pass: f32 -> f16 for K and V ----
__global__ void __launch_bounds__(256) convert_kv(const float* __restrict__ K,
                                                  const float* __restrict__ V)
{
    size_t i = ((size_t)blockIdx.x * 256 + threadIdx.x) * 8;
    float4 a = *(const float4*)(K + i);
    float4 b = *(const float4*)(K + i + 4);
    *(uint4*)(KhBuf + i) = make_uint4(h2(a.x, a.y), h2(a.z, a.w), h2(b.x, b.y), h2(b.z, b.w));
    a = *(const float4*)(V + i);
    b = *(const float4*)(V + i + 4);
    *(uint4*)(VhBuf + i) = make_uint4(h2(a.x, a.y), h2(a.z, a.w), h2(b.x, b.y), h2(b.z, b.w));
}

__global__ void __launch_bounds__(NTH, 1)
spatial_attn_h5(const float* __restrict__ Qg, float* __restrict__ Og)
{
    extern __shared__ char smem[];
    const uint32_t sb = (uint32_t)__cvta_generic_to_shared(smem);
    const int tid  = threadIdx.x;
    const int warp = tid >> 5;
    const int lane = tid & 31;
    const int g    = lane >> 2;
    const int tg   = lane & 3;

    const size_t boff = (size_t)blockIdx.y * CD * HW;
    const float*  Qb  = Qg + boff;
    float*        Ob  = Og + boff;
    const __half* KhB = KhBuf + boff;
    const __half* VhB = VhBuf + boff;

    const int tw = blockIdx.x * TT + warp * 16;   // this warp's first t

    // ---- Q A-fragments, scaled by (1/sqrt(C))*log2(e), fp16 ----
    const float S = (float)(0.08838834764831845 * 1.4426950408889634);
    uint32_t qa[8][4];
#pragma unroll
    for (int kt = 0; kt < 8; kt++) {
        const float* q0 = Qb + (size_t)(kt * 16 + 2 * tg) * HW;
        qa[kt][0] = h2(q0[tw + g] * S,              q0[HW + tw + g] * S);
        qa[kt][1] = h2(q0[tw + g + 8] * S,          q0[HW + tw + g + 8] * S);
        qa[kt][2] = h2(q0[8 * HW + tw + g] * S,     q0[9 * HW + tw + g] * S);
        qa[kt][3] = h2(q0[8 * HW + tw + g + 8] * S, q0[9 * HW + tw + g + 8] * S);
    }

    float o[16][4];
#pragma unroll
    for (int ne = 0; ne < 16; ne++)
#pragma unroll
        for (int r = 0; r < 4; r++) o[ne][r] = 0.f;
    float l0 = 0.f, l1 = 0.f;

    // ---- cp.async stage loader: 1024 16B-chunks per tensor, 4+4 per thread ----
    auto issueStage = [&](int st) {
        const int buf = st % NSTAGE;
        const uint32_t kdst = sb + buf * STAGE_B;
        const uint32_t vdst = kdst + TILE_B;
        const __half* ks = KhB + (size_t)st * BS;
        const __half* vs = VhB + (size_t)st * BS;
#pragma unroll
        for (int p = 0; p < 4; p++) {
            int ci  = tid + p * NTH;
            int row = ci >> 3;
            int ch  = ci & 7;
            uint32_t d = (uint32_t)(row * RS + ch * 16);
            size_t   s = (size_t)row * HW + ch * 8;
            cpasync16(kdst + d, ks + s);
            cpasync16(vdst + d, vs + s);
        }
    };

    // ---- GEMM1 for one 32-s half of a stage (identical to R9 inner) ----
    auto gemm1 = [&](int buf, int h, float sc[4][4]) {
#pragma unroll
        for (int ns = 0; ns < 4; ns++)
#pragma unroll
            for (int r = 0; r < 4; r++) sc[ns][r] = 0.f;
        const uint32_t ka = sb + buf * STAGE_B + lane * RS + h * 64;
#pragma unroll
        for (int i = 0; i < 4; i++) {
            uint32_t f[4][4];
#pragma unroll
            for (int ns = 0; ns < 4; ns++)
                ldsm4t(f[ns][0], f[ns][1], f[ns][2], f[ns][3],
                       ka + i * (32 * RS) + ns * 16);
#pragma unroll
            for (int ns = 0; ns < 4; ns++) {
                mma16816(sc[ns], qa[2 * i],     f[ns][0], f[ns][1]);
                mma16816(sc[ns], qa[2 * i + 1], f[ns][2], f[ns][3]);
            }
        }
    };

    // ---- GEMM2 for one 32-s half: O += P·V ----
    auto gemm2 = [&](int buf, int h, const uint32_t pa[2][4]) {
        const uint32_t va = sb + buf * STAGE_B + TILE_B
                          + (lane & 7) * RS + (lane >> 3) * 16 + h * 64;
#pragma unroll
        for (int np = 0; np < 8; np++) {
            uint32_t f0[4], f1[4];
            ldsm4(f0[0], f0[1], f0[2], f0[3], va + (2 * np)     * (8 * RS));
            ldsm4(f1[0], f1[1], f1[2], f1[3], va + (2 * np + 1) * (8 * RS));
            mma16816(o[2 * np],     pa[0], f0[0], f0[1]);
            mma16816(o[2 * np],     pa[1], f0[2], f0[3]);
            mma16816(o[2 * np + 1], pa[0], f1[0], f1[1]);
            mma16816(o[2 * np + 1], pa[1], f1[2], f1[3]);
        }
    };

    // ---- prologue: fill 2 stages, then GEMM1(stage0, half0) ----
    issueStage(0); asm volatile("cp.async.commit_group;");
    issueStage(1); asm volatile("cp.async.commit_group;");
    asm volatile("cp.async.wait_group 1;");
    __syncthreads();

    float sc[4][4];
    gemm1(0, 0, sc);

    for (int vb = 0; vb < NVB; vb++) {
        const int st  = vb >> 1;
        const int buf = st % NSTAGE;
        const int h   = vb & 1;

        // ---- softmax of block vb (scores pre-scaled to log2 domain) ----
        uint32_t pa[2][4];
#pragma unroll
        for (int ns = 0; ns < 4; ns++) {
            float p0 = ex2(sc[ns][0]);
            float p1 = ex2(sc[ns][1]);
            float p2 = ex2(sc[ns][2]);
            float p3 = ex2(sc[ns][3]);
            l0 += p0 + p1;
            l1 += p2 + p3;
            pa[ns >> 1][(ns & 1) * 2 + 0] = h2(p0, p1);   // rows g
            pa[ns >> 1][(ns & 1) * 2 + 1] = h2(p2, p3);   // rows g+8
        }

        // ---- GEMM1 of next block ahead of GEMM2 (barrier only on stage cross) ----
        if (vb + 1 < NVB) {
            if (h == 1) {
                asm volatile("cp.async.wait_group 1;");
                __syncthreads();
                gemm1((st + 1) % NSTAGE, 0, sc);
            } else {
                gemm1(buf, 1, sc);
            }
        }

        // ---- GEMM2 of block vb ----
        gemm2(buf, h, pa);

        // ---- end of stage: prefetch st+2 (buffer (st+2)%3, not in use) ----
        if (h == 1) {
            if (st + 2 < NST) issueStage(st + 2);
            asm volatile("cp.async.commit_group;");
        }
    }

    // ---- epilogue: finish row sums (quad reduce), normalize, store ----
    l0 += __shfl_xor_sync(0xffffffffu, l0, 1);
    l0 += __shfl_xor_sync(0xffffffffu, l0, 2);
    l1 += __shfl_xor_sync(0xffffffffu, l1, 1);
    l1 += __shfl_xor_sync(0xffffffffu, l1, 2);
    const float i0 = 1.0f / l0;
    const float i1 = 1.0f / l1;

#pragma unroll
    for (int ne = 0; ne < 16; ne++) {
        int e = ne * 8 + 2 * tg;
        Ob[(size_t)e       * HW + tw + g]     = o[ne][0] * i0;
        Ob[(size_t)(e + 1) * HW + tw + g]     = o[ne][1] * i0;
        Ob[(size_t)e       * HW + tw + g + 8] = o[ne][2] * i1;
        Ob[(size_t)(e + 1) * HW + tw + g + 8] = o[ne][3] * i1;
    }
}

extern "C" void kernel_launch(void* const* d_in, const int* in_sizes, int n_in,
                              void* d_out, int out_size)
{
    const float* K = (const float*)d_in[0];   // key
    const float* Q = (const float*)d_in[1];   // query
    const float* V = (const float*)d_in[2];   // value
    float*       O = (float*)d_out;

    const int nbatch = in_sizes[0] / (CD * HW);   // 4

    // pre-pass: K,V -> fp16 device buffers
    convert_kv<<<ELEMS / (256 * 8), 256>>>(K, V);

    cudaFuncSetAttribute(spatial_attn_h5,
                         cudaFuncAttributeMaxDynamicSharedMemorySize, SMEM_BYTES);
    dim3 grid(HW / TT, nbatch);   // (32, 4) = 128 CTAs
    spatial_attn_h5<<<grid, NTH, SMEM_BYTES>>>(Q, O);
}